// round 17
// baseline (speedup 1.0000x reference)
#include <cuda_runtime.h>
#include <cuda_fp16.h>
#include <cuda.h>
#include <cstdint>

#define NTOK   16384
#define HID    1024
#define HDIM   64

// ---------------- scratch (device globals; no cudaMalloc allowed) -------------
__device__ __align__(256) __half g_xh[NTOK * HID];
__device__ __align__(256) __half g_wh[4 * HID * HID];
__device__ __align__(256) __half g_q[NTOK * HID];
__device__ __align__(256) __half g_k[NTOK * HID];
__device__ __align__(256) __half g_v[NTOK * HID];
__device__ __align__(256) __half g_ah[NTOK * HID];

// ---------------- PTX helpers (plain-sm_103-legal) -----------------------------
__device__ __forceinline__ uint32_t smem_u32(const void* p) {
    uint32_t a;
    asm("{ .reg .u64 t; cvta.to.shared.u64 t, %1; cvt.u32.u64 %0, t; }" : "=r"(a) : "l"(p));
    return a;
}

__device__ __forceinline__ void cp_async16(uint32_t saddr, const void* gptr) {
    asm volatile("cp.async.cg.shared.global [%0], [%1], 16;"
                 :: "r"(saddr), "l"(__cvta_generic_to_global(gptr)) : "memory");
}
__device__ __forceinline__ void cp_commit() {
    asm volatile("cp.async.commit_group;" ::: "memory");
}
template <int N>
__device__ __forceinline__ void cp_wait() {
    asm volatile("cp.async.wait_group %0;" :: "n"(N) : "memory");
}

__device__ __forceinline__ void mbar_init(uint32_t mbar, uint32_t cnt) {
    asm volatile("mbarrier.init.shared.b64 [%0], %1;" :: "r"(mbar), "r"(cnt) : "memory");
}
__device__ __forceinline__ void mbar_expect_tx(uint32_t mbar, uint32_t bytes) {
    asm volatile("mbarrier.arrive.expect_tx.shared.b64 _, [%0], %1;"
                 :: "r"(mbar), "r"(bytes) : "memory");
}
__device__ __forceinline__ void mbar_wait(uint32_t mbar, uint32_t parity) {
    uint32_t done;
    asm volatile("{\n\t.reg .pred p;\n\tmbarrier.try_wait.parity.acquire.cta.shared::cta.b64 p, [%1], %2;\n\tselp.b32 %0, 1, 0, p;\n\t}"
                 : "=r"(done) : "r"(mbar), "r"(parity) : "memory");
    while (!done) {
        asm volatile("{\n\t.reg .pred p;\n\tmbarrier.try_wait.parity.acquire.cta.shared::cta.b64 p, [%1], %2, 0x989680;\n\tselp.b32 %0, 1, 0, p;\n\t}"
                     : "=r"(done) : "r"(mbar), "r"(parity) : "memory");
    }
}

__device__ __forceinline__ void tma_load_2d(uint32_t smem_addr, const CUtensorMap* tmap,
                                            int x, int y, uint32_t mbar) {
    asm volatile("cp.async.bulk.tensor.2d.shared::cta.global.tile.mbarrier::complete_tx::bytes "
                 "[%0], [%1, {%2, %3}], [%4];"
                 :: "r"(smem_addr), "l"(tmap), "r"(x), "r"(y), "r"(mbar) : "memory");
}

__device__ __forceinline__ void ldsm4(uint32_t addr, uint32_t* r) {
    asm volatile("ldmatrix.sync.aligned.m8n8.x4.shared.b16 {%0,%1,%2,%3}, [%4];"
                 : "=r"(r[0]), "=r"(r[1]), "=r"(r[2]), "=r"(r[3]) : "r"(addr));
}
__device__ __forceinline__ void ldsm4t(uint32_t addr, uint32_t* r) {
    asm volatile("ldmatrix.sync.aligned.m8n8.x4.trans.shared.b16 {%0,%1,%2,%3}, [%4];"
                 : "=r"(r[0]), "=r"(r[1]), "=r"(r[2]), "=r"(r[3]) : "r"(addr));
}

// D += A * B  (m16n8k16, fp16 in, fp32 acc)
__device__ __forceinline__ void mma_fp16(float* c, const uint32_t* a, const uint32_t* b) {
    asm volatile("mma.sync.aligned.m16n8k16.row.col.f32.f16.f16.f32 "
                 "{%0,%1,%2,%3}, {%4,%5,%6,%7}, {%8,%9}, {%0,%1,%2,%3};"
                 : "+f"(c[0]), "+f"(c[1]), "+f"(c[2]), "+f"(c[3])
                 : "r"(a[0]), "r"(a[1]), "r"(a[2]), "r"(a[3]), "r"(b[0]), "r"(b[1]));
}

// ---------------- GEMM geometry (R12 known-good pipeline) ----------------------
// CTA tile 128x128, 4 warps (2x2 of 64x64), 128 threads, BK=64.
// Slot = A 16KB + B 16KB = 32KB via 2 TMA loads; 3 slots; 2 CTAs/SM.
#define BM         128
#define BN         128
#define BK         64
#define NTHREADS   128
#define A_BYTES    16384
#define SLOT_BYTES 32768
#define NSLOTS     3
#define SMEM_BYTES (1024 + NSLOTS * SLOT_BYTES)
#define NSTAGES    (HID / BK)     // 16

// ldmatrix.x4 address (SW128 layout, 128B rows): R = first row, kb = k16 byte offset
__device__ __forceinline__ uint32_t frag_addr(uint32_t base, int R, int kb, int lane) {
    const int row = R + (lane & 7) + ((lane >> 3) & 1) * 8;
    const int kc  = kb + (lane >> 4) * 16;
    const uint32_t bo = (uint32_t)(row * 128 + kc);
    return base + (bo ^ (uint32_t)((row & 7) << 4));
}

// Load all fragments for one k16 step (8 ldsm.x4): B 64-col strip + A 64-row strip.
__device__ __forceinline__ void load_frags(uint32_t b[8][2], uint32_t a[4][4],
                                           uint32_t sA, uint32_t sB, int kb,
                                           int wm, int wn, int lane) {
#pragma unroll
    for (int p = 0; p < 4; ++p) {
        uint32_t r[4];
        ldsm4(frag_addr(sB, wn + p * 16, kb, lane), r);
        b[2 * p][0] = r[0]; b[2 * p + 1][0] = r[1];
        b[2 * p][1] = r[2]; b[2 * p + 1][1] = r[3];
    }
#pragma unroll
    for (int fm = 0; fm < 4; ++fm)
        ldsm4(frag_addr(sA, wm + fm * 16, kb, lane), a[fm]);
}

// ---------------- fp16 tensor-core GEMM: TMA + frag double-buffer --------------
// Sync/refill position is EXACTLY R12's (after the full k-loop of the stage).
template <typename OutT>
__device__ __forceinline__ void gemm_tma(const CUtensorMap* tA, const CUtensorMap* tB,
                                         int a_row0, int b_row0, OutT* __restrict__ C)
{
    extern __shared__ char smem[];
    const uint32_t sbase = smem_u32(smem);
    const uint32_t mb    = sbase;            // 3 mbarriers at +0,+8,+16
    const uint32_t slots = sbase + 1024;
    const int tid  = threadIdx.x;
    const int wid  = tid >> 5;
    const int lane = tid & 31;
    const int wm   = (wid >> 1) * 64;
    const int wn   = (wid & 1) * 64;

    if (tid == 0) {
        mbar_init(mb + 0, 1);
        mbar_init(mb + 8, 1);
        mbar_init(mb + 16, 1);
    }
    __syncthreads();

    if (tid == 0) {
#pragma unroll
        for (int s = 0; s < NSLOTS; ++s) {
            const uint32_t sl = slots + s * SLOT_BYTES;
            mbar_expect_tx(mb + s * 8, SLOT_BYTES);
            tma_load_2d(sl,           tA, s * BK, a_row0, mb + s * 8);
            tma_load_2d(sl + A_BYTES, tB, s * BK, b_row0, mb + s * 8);
        }
    }

    float acc[4][8][4];
#pragma unroll
    for (int i = 0; i < 4; ++i)
#pragma unroll
        for (int j = 0; j < 8; ++j)
#pragma unroll
            for (int r = 0; r < 4; ++r) acc[i][j][r] = 0.f;

#pragma unroll 1
    for (int t = 0; t < NSTAGES; ++t) {
        const int s = t % NSLOTS;
        mbar_wait(mb + s * 8, (t / NSLOTS) & 1);

        const uint32_t sA = slots + s * SLOT_BYTES;
        const uint32_t sB = sA + A_BYTES;

        uint32_t bf[2][8][2], af[2][4][4];
        load_frags(bf[0], af[0], sA, sB, 0, wm, wn, lane);

#pragma unroll
        for (int ks = 0; ks < BK / 16; ++ks) {
            const int cur = ks & 1, nxt = cur ^ 1;
            if (ks < 3)
                load_frags(bf[nxt], af[nxt], sA, sB, (ks + 1) * 32, wm, wn, lane);
#pragma unroll
            for (int fm = 0; fm < 4; ++fm)
#pragma unroll
                for (int fn = 0; fn < 8; ++fn)
                    mma_fp16(acc[fm][fn], af[cur][fm], bf[cur][fn]);
        }

        __syncthreads();                       // R12 position: slot s free everywhere
        if (t + NSLOTS < NSTAGES && tid == 0) {
            mbar_expect_tx(mb + s * 8, SLOT_BYTES);
            tma_load_2d(sA,           tA, (t + NSLOTS) * BK, a_row0, mb + s * 8);
            tma_load_2d(sA + A_BYTES, tB, (t + NSLOTS) * BK, b_row0, mb + s * 8);
        }
    }

    // epilogue: register fragments -> gmem
#pragma unroll
    for (int fm = 0; fm < 4; ++fm) {
        const int r0 = a_row0 + wm + fm * 16 + (lane >> 2);
        const int cb = (b_row0 % HID);   // bn within the 1024-wide output
#pragma unroll
        for (int fn = 0; fn < 8; ++fn) {
            const int c0 = cb + wn + fn * 8 + (lane & 3) * 2;
            if constexpr (sizeof(OutT) == 2) {
                __half2 h0 = __floats2half2_rn(acc[fm][fn][0], acc[fm][fn][1]);
                __half2 h1 = __floats2half2_rn(acc[fm][fn][2], acc[fm][fn][3]);
                *(__half2*)&C[(size_t)r0 * HID + c0]       = h0;
                *(__half2*)&C[(size_t)(r0 + 8) * HID + c0] = h1;
            } else {
                float2 v0 = { acc[fm][fn][0], acc[fm][fn][1] };
                float2 v1 = { acc[fm][fn][2], acc[fm][fn][3] };
                *(float2*)&C[(size_t)r0 * HID + c0]       = v0;
                *(float2*)&C[(size_t)(r0 + 8) * HID + c0] = v1;
            }
        }
    }
}

__global__ void __launch_bounds__(NTHREADS, 2)
tc_qkv(const __grid_constant__ CUtensorMap tmA, const __grid_constant__ CUtensorMap tmB) {
    __half* C = (blockIdx.z == 0) ? g_q : (blockIdx.z == 1) ? g_k : g_v;
    gemm_tma<__half>(&tmA, &tmB,
                     blockIdx.y * BM,
                     blockIdx.z * HID + blockIdx.x * BN,   // row in 4096-row W map
                     C);
}

__global__ void __launch_bounds__(NTHREADS, 2)
tc_o(const __grid_constant__ CUtensorMap tmA, const __grid_constant__ CUtensorMap tmB,
     float* __restrict__ out) {
    gemm_tma<float>(&tmA, &tmB,
                    blockIdx.y * BM,
                    3 * HID + blockIdx.x * BN,
                    out);
}

// ---------------- fused fp32 -> fp16 conversion (x + all 4 weights) ------------
#define XCH (NTOK * HID / 4)     // float4 chunks in x
#define WCH (HID * HID / 4)      // float4 chunks per weight
__global__ void __launch_bounds__(256) conv_all(const float* __restrict__ x,
                                                const float* __restrict__ wq,
                                                const float* __restrict__ wk,
                                                const float* __restrict__ wv,
                                                const float* __restrict__ wo) {
    const size_t id = (size_t)blockIdx.x * 256 + threadIdx.x;
    const float* src;
    __half* dst;
    size_t off;
    if (id < XCH) {
        src = x; dst = g_xh; off = id;
    } else {
        const size_t wi = (id - XCH) / WCH;
        off = (id - XCH) % WCH;
        src = (wi == 0) ? wq : (wi == 1) ? wk : (wi == 2) ? wv : wo;
        dst = g_wh + wi * (size_t)HID * HID;
    }
    const float4 v = ((const float4*)src)[off];
    __half2 p0 = __floats2half2_rn(v.x, v.y);
    __half2 p1 = __floats2half2_rn(v.z, v.w);
    uint2 pk = { *(uint32_t*)&p0, *(uint32_t*)&p1 };
    *(uint2*)(dst + off * 4) = pk;
}

// ---------------- tensor-core per-token attention (validated R9) ---------------
__global__ void __launch_bounds__(256) attn_kernel() {
    __shared__ __align__(128) char sm[8 * 3 * 2048];
    const uint32_t sbase = smem_u32(sm);
    const int tid  = threadIdx.x;
    const int lane = tid & 31;
    const int wid  = tid >> 5;
    const size_t tok0 = (size_t)blockIdx.x * 8;

#pragma unroll
    for (int j = 0; j < 12; ++j) {
        const int id   = tid + j * 256;
        const int w    = id / 384;
        const int rem  = id - w * 384;
        const int tile = rem >> 7;
        const int c    = rem & 127;
        const int row  = c >> 3;
        const int c8   = c & 7;
        const __half* src = (tile == 0 ? g_q : tile == 1 ? g_k : g_v)
                          + (tok0 + w) * HID + row * HDIM + c8 * 8;
        const uint32_t bo = (uint32_t)(row * 128 + c8 * 16);
        const uint32_t sw = bo ^ (uint32_t)((row & 7) << 4);
        cp_async16(sbase + (uint32_t)(w * 3 + tile) * 2048 + sw, src);
    }
    cp_commit();
    cp_wait<0>();
    __syncthreads();

    const uint32_t qb = sbase + (uint32_t)(wid * 3 + 0) * 2048;
    const uint32_t kb = sbase + (uint32_t)(wid * 3 + 1) * 2048;
    const uint32_t vb = sbase + (uint32_t)(wid * 3 + 2) * 2048;

    float sc[2][4];
#pragma unroll
    for (int i = 0; i < 2; ++i)
#pragma unroll
        for (int r = 0; r < 4; ++r) sc[i][r] = 0.f;

#pragma unroll
    for (int s = 0; s < 4; ++s) {
        uint32_t a[4], b[4];
        ldsm4(frag_addr(qb, 0, s * 32, lane), a);
        ldsm4(frag_addr(kb, 0, s * 32, lane), b);
        uint32_t b0[2] = { b[0], b[2] };
        uint32_t b1[2] = { b[1], b[3] };
        mma_fp16(sc[0], a, b0);
        mma_fp16(sc[1], a, b1);
    }

    float mlo = fmaxf(fmaxf(sc[0][0], sc[0][1]), fmaxf(sc[1][0], sc[1][1]));
    float mhi = fmaxf(fmaxf(sc[0][2], sc[0][3]), fmaxf(sc[1][2], sc[1][3]));
#pragma unroll
    for (int off = 1; off <= 2; off <<= 1) {
        mlo = fmaxf(mlo, __shfl_xor_sync(0xffffffffu, mlo, off));
        mhi = fmaxf(mhi, __shfl_xor_sync(0xffffffffu, mhi, off));
    }
    float plo[4], phi[4];
    plo[0] = __expf(0.125f * (sc[0][0] - mlo));
    plo[1] = __expf(0.125f * (sc[0][1] - mlo));
    plo[2] = __expf(0.125f * (sc[1][0] - mlo));
    plo[3] = __expf(0.125f * (sc[1][1] - mlo));
    phi[0] = __expf(0.125f * (sc[0][2] - mhi));
    phi[1] = __expf(0.125f * (sc[0][3] - mhi));
    phi[2] = __expf(0.125f * (sc[1][2] - mhi));
    phi[3] = __expf(0.125f * (sc[1][3] - mhi));
    float slo = plo[0] + plo[1] + plo[2] + plo[3];
    float shi = phi[0] + phi[1] + phi[2] + phi[3];
#pragma unroll
    for (int off = 1; off <= 2; off <<= 1) {
        slo += __shfl_xor_sync(0xffffffffu, slo, off);
        shi += __shfl_xor_sync(0xffffffffu, shi, off);
    }
    const float rlo = 1.f / slo, rhi = 1.f / shi;

    uint32_t pa[4];
    {
        __half2 h;
        h = __floats2half2_rn(plo[0] * rlo, plo[1] * rlo); pa[0] = *(uint32_t*)&h;
        h = __floats2half2_rn(phi[0] * rhi, phi[1] * rhi); pa[1] = *(uint32_t*)&h;
        h = __floats2half2_rn(plo[2] * rlo, plo[3] * rlo); pa[2] = *(uint32_t*)&h;
        h = __floats2half2_rn(phi[2] * rhi, phi[3] * rhi); pa[3] = *(uint32_t*)&h;
    }

    float o[8][4];
#pragma unroll
    for (int j = 0; j < 8; ++j)
#pragma unroll
        for (int r = 0; r < 4; ++r) o[j][r] = 0.f;

#pragma unroll
    for (int j2 = 0; j2 < 4; ++j2) {
        uint32_t b[4];
        ldsm4t(frag_addr(vb, 0, j2 * 32, lane), b);
        uint32_t b0[2] = { b[0], b[1] };
        uint32_t b1[2] = { b[2], b[3] };
        mma_fp16(o[2 * j2],     pa, b0);
        mma_fp16(o[2 * j2 + 1], pa, b1);
    }

    char* stp = sm + wid * 3 * 2048;
    {
        const int r  = lane >> 2;
        const int cb = (lane & 3) * 4;
#pragma unroll
        for (int j = 0; j < 8; ++j) {
            __half2 lo2 = __floats2half2_rn(o[j][0], o[j][1]);
            __half2 hi2 = __floats2half2_rn(o[j][2], o[j][3]);
            *(__half2*)(stp + r * 144 + j * 16 + cb)       = lo2;
            *(__half2*)(stp + (r + 8) * 144 + j * 16 + cb) = hi2;
        }
    }
    __syncwarp();
    {
        __half* gdst = g_ah + (tok0 + wid) * HID;
#pragma unroll
        for (int l = 0; l < 4; ++l) {
            const int id  = lane + l * 32;
            const int row = id >> 3;
            const int c8  = id & 7;
            const uint4 v = *(const uint4*)(stp + row * 144 + c8 * 16);
            *(uint4*)(gdst + row * HDIM + c8 * 8) = v;
        }
    }
}

// ---------------- host: tensor-map creation + launch ---------------------------
typedef CUresult (*PFN_encodeTiled)(CUtensorMap*, CUtensorMapDataType, cuuint32_t,
                                    void*, const cuuint64_t*, const cuuint64_t*,
                                    const cuuint32_t*, const cuuint32_t*,
                                    CUtensorMapInterleave, CUtensorMapSwizzle,
                                    CUtensorMapL2promotion, CUtensorMapFloatOOBfill);

static void make_map(PFN_encodeTiled enc, CUtensorMap* tm, void* base, uint64_t rows) {
    cuuint64_t dims[2]    = { (cuuint64_t)HID, (cuuint64_t)rows };
    cuuint64_t strides[1] = { (cuuint64_t)(HID * sizeof(__half)) };
    cuuint32_t box[2]     = { BK, BM };      // 64 fp16 = 128B (SW128 max), 128 rows
    cuuint32_t estr[2]    = { 1, 1 };
    enc(tm, CU_TENSOR_MAP_DATA_TYPE_FLOAT16, 2, base, dims, strides, box, estr,
        CU_TENSOR_MAP_INTERLEAVE_NONE, CU_TENSOR_MAP_SWIZZLE_128B,
        CU_TENSOR_MAP_L2_PROMOTION_L2_128B, CU_TENSOR_MAP_FLOAT_OOB_FILL_NONE);
}

extern "C" void kernel_launch(void* const* d_in, const int* in_sizes, int n_in,
                              void* d_out, int out_size)
{
    const float* x  = (const float*)d_in[0];
    const float* wq = (const float*)d_in[1];
    const float* wk = (const float*)d_in[2];
    const float* wv = (const float*)d_in[3];
    const float* wo = (const float*)d_in[4];
    float* out = (float*)d_out;

    void* fn = nullptr;
#if CUDART_VERSION >= 12050
    cudaDriverEntryPointQueryResult qr;
    cudaGetDriverEntryPointByVersion("cuTensorMapEncodeTiled", &fn, 12000,
                                     cudaEnableDefault, &qr);
#else
    cudaGetDriverEntryPoint("cuTensorMapEncodeTiled", &fn, cudaEnableDefault, nullptr);
#endif
    PFN_encodeTiled enc = (PFN_encodeTiled)fn;

    void *pxh, *pwh, *pah;
    cudaGetSymbolAddress(&pxh, g_xh);
    cudaGetSymbolAddress(&pwh, g_wh);
    cudaGetSymbolAddress(&pah, g_ah);

    alignas(64) CUtensorMap tmX, tmW, tmA;
    make_map(enc, &tmX, pxh, NTOK);
    make_map(enc, &tmW, pwh, 4 * HID);
    make_map(enc, &tmA, pah, NTOK);

    cudaFuncSetAttribute(tc_qkv, cudaFuncAttributeMaxDynamicSharedMemorySize, SMEM_BYTES);
    cudaFuncSetAttribute(tc_o,   cudaFuncAttributeMaxDynamicSharedMemorySize, SMEM_BYTES);

    conv_all<<<(XCH + 4 * WCH) / 256, 256>>>(x, wq, wk, wv, wo);

    dim3 gqkv(HID / BN, NTOK / BM, 3);     // (8, 128, 3)
    tc_qkv<<<gqkv, NTHREADS, SMEM_BYTES>>>(tmX, tmW);

    attn_kernel<<<NTOK / 8, 256>>>();

    dim3 go(HID / BN, NTOK / BM, 1);       // (8, 128, 1)
    tc_o<<<go, NTHREADS, SMEM_BYTES>>>(tmA, tmW, out);
}